// round 8
// baseline (speedup 1.0000x reference)
#include <cuda_runtime.h>
#include <cuda_bf16.h>
#include <cstdint>

// ---------------------------------------------------------------------------
// PPEG: out = dwconv7(x) + x + dwconv5(x) + dwconv3(x)  (depthwise, per-channel)
// Folded into ONE 7x7x7 depthwise conv per channel + combined bias.
// 1 output (16 d-values) per thread; ALL dd taps packed fma.rn.f32x2:
//   even dd -> aligned pairs (0,1)..(14,15); odd dd -> staggered pairs
//   (1,2)..(13,14) whose inputs are ALSO aligned zv pairs, + 2 scalar taps.
// 3 CTAs/SM (24 warps) via SDP=26 / 4-row tiles / 85-reg cap.
//
// x layout  (per channel c): volume[d][h][w], d=16, h=64, w=64 (w contiguous)
// out layout(per channel c): [h][w][d] with d contiguous (stride-1)
// ---------------------------------------------------------------------------

#define NCH   512
#define DD    16
#define HH    64
#define WW    64
#define VOL   (DD*HH*WW)      // 65536 per channel

#define WSTRIDE 352           // per-channel slot in g_wcomb (343 taps + bias)
__device__ float g_wcomb[NCH * WSTRIDE];

typedef unsigned long long u64;
typedef unsigned int u32;

#define FMA2P(acc_, alo_, ahi_, w2_) \
    asm("{\n\t.reg .b64 _a;\n\tmov.b64 _a, {%1, %2};\n\t" \
        "fma.rn.f32x2 %0, _a, %3, %0;\n\t}" \
        : "+l"(acc_) : "f"(alo_), "f"(ahi_), "l"(w2_))

// -------------------- weight folding --------------------
__global__ void fold_weights_kernel(const float* __restrict__ w7,
                                    const float* __restrict__ b7,
                                    const float* __restrict__ w5,
                                    const float* __restrict__ b5,
                                    const float* __restrict__ w3,
                                    const float* __restrict__ b3) {
    int c = blockIdx.x;
    for (int t = threadIdx.x; t < 343; t += blockDim.x) {
        int dd = t / 49;
        int r  = t % 49;
        int dh = r / 7;
        int dw = r % 7;
        float v = w7[c * 343 + t];
        if (dd >= 1 && dd <= 5 && dh >= 1 && dh <= 5 && dw >= 1 && dw <= 5)
            v += w5[c * 125 + (dd - 1) * 25 + (dh - 1) * 5 + (dw - 1)];
        if (dd >= 2 && dd <= 4 && dh >= 2 && dh <= 4 && dw >= 2 && dw <= 4)
            v += w3[c * 27 + (dd - 2) * 9 + (dh - 2) * 3 + (dw - 2)];
        if (t == 171) v += 1.0f;   // identity: center tap (3,3,3)
        g_wcomb[c * WSTRIDE + t] = v;
    }
    if (threadIdx.x == 0)
        g_wcomb[c * WSTRIDE + 343] = b7[c] + b5[c] + b3[c];
}

// -------------------- main conv --------------------
// CTA: one channel, 4 consecutive h rows, full W, full D.  256 threads.
// Thread (w, hl): one output column of 16 d-values at h = h0+hl.
// Smem tile d-innermost: [sh=10][sw=70][sd_pad=26], halo 3 each side, zero-padded.
// Weights in smem as (w,w) u64 pairs grouped per (dh,dw): slot stride 8 u64.
#define SM_D  22
#define SDP   26
#define SM_H  10
#define SM_W  70
#define NCOLS (SM_H * SM_W)                  // 700 (sh,sw) columns
#define TILE_FLOATS (NCOLS * SDP)            // 18200
#define WT_U64S (49 * 8)                     // 392 u64 (7 dd + pad per (dh,dw))
#define SMEM_BYTES (TILE_FLOATS * 4 + WT_U64S * 8 + 16)   // ~74.3 KB
#define NTHR  256

__global__ __launch_bounds__(NTHR, 3)
void ppeg_conv_kernel(const float* __restrict__ x, float* __restrict__ out) {
    extern __shared__ float smem[];
    float* sx  = smem;                        // transposed input tile
    u64*  swt2 = (u64*)(smem + TILE_FLOATS);  // weight pairs, [(dh*7+dw)*8 + dd]
    float* sbias = (float*)(swt2 + WT_U64S);

    const int c   = blockIdx.y;
    const int h0  = blockIdx.x * 4;
    const int tid = threadIdx.x;

    const float* __restrict__ xc = x + (size_t)c * VOL;

    // folded weights for this channel -> duplicated pairs, grouped per (dh,dw)
    for (int t = tid; t < 343; t += NTHR) {
        int dd = t / 49;               // original layout [dd][dh][dw]
        int r  = t % 49;               // r = dh*7+dw
        float wv = g_wcomb[c * WSTRIDE + t];
        ((float2*)swt2)[r * 8 + dd] = make_float2(wv, wv);
    }
    if (tid == 0) sbias[0] = g_wcomb[c * WSTRIDE + 343];

    // ---- tile load: one (sh,sw) column of 22 d-values per iteration ----
    for (int col = tid; col < NCOLS; col += NTHR) {
        int sh = col / SM_W;
        int sw = col - sh * SM_W;
        int gh = h0 + sh - 3;
        int gw = sw - 3;
        bool okhw = ((unsigned)gh < (unsigned)HH) && ((unsigned)gw < (unsigned)WW);
        const float* gp = xc + (gh * WW + gw);

        float z[SM_D];
#pragma unroll
        for (int sd = 0; sd < SM_D; ++sd) {
            int gd = sd - 3;
            float v = 0.0f;
            if (gd >= 0 && gd < DD)            // compile-time predicate
                v = okhw ? __ldg(gp + gd * (HH * WW)) : 0.0f;
            z[sd] = v;
        }

        float2* sp = (float2*)(sx + col * SDP);   // 8B aligned
#pragma unroll
        for (int m = 0; m < 11; ++m)
            sp[m] = make_float2(z[2 * m], z[2 * m + 1]);
    }
    __syncthreads();

    const int w  = tid & 63;   // 0..63
    const int hl = tid >> 6;   // 0..3  -> output at h0+hl

    // accumulators: E pairs (0,1)..(14,15) bias-seeded; Q pairs (1,2)..(13,14); 2 scalars
    u64 E[8], Q[7];
    float s0 = 0.0f, s15 = 0.0f;
    {
        float b = sbias[0];
        u64 b2; asm("mov.b64 %0, {%1, %2};" : "=l"(b2) : "f"(b), "f"(b));
#pragma unroll
        for (int j = 0; j < 8; ++j) E[j] = b2;
#pragma unroll
        for (int j = 0; j < 7; ++j) Q[j] = 0ull;
    }

#pragma unroll 1
    for (int dh = 0; dh < 7; ++dh) {
        const float* rowbase = sx + ((hl + dh) * SM_W + w) * SDP;
        const u64*   wbase   = swt2 + (dh * 7) * 8;
#pragma unroll
        for (int dw = 0; dw < 7; ++dw) {
            // 22-deep d-column as 11 LDS.64
            float2 zv[11];
            const float2* col2 = (const float2*)(rowbase + dw * SDP);
#pragma unroll
            for (int m = 0; m < 11; ++m) zv[m] = col2[m];

            const u64* wcol = wbase + dw * 8;   // 7 contiguous dd pairs
#pragma unroll
            for (int s = 0; s < 4; ++s) {       // even dd = 2s
                const u64 w2 = wcol[2 * s];
#pragma unroll
                for (int j = 0; j < 8; ++j)
                    FMA2P(E[j], zv[j + s].x, zv[j + s].y, w2);
            }
#pragma unroll
            for (int s = 0; s < 3; ++s) {       // odd dd = 2s+1
                const u64 w2 = wcol[2 * s + 1];
                float wlo, whi;
                asm("mov.b64 {%0, %1}, %2;" : "=f"(wlo), "=f"(whi) : "l"(w2));
#pragma unroll
                for (int j = 0; j < 7; ++j)     // Q_j inputs: zv[j+s+1] (aligned)
                    FMA2P(Q[j], zv[j + s + 1].x, zv[j + s + 1].y, w2);
                s0  = fmaf(zv[s].y,     wlo, s0);   // out0:  z[2s+1]
                s15 = fmaf(zv[8 + s].x, whi, s15);  // out15: z[16+2s]
            }
        }
    }

    // merge E/Q banks and store: out[c][(h*64+w)*16 + d]
    float e[16], q[14];
#pragma unroll
    for (int j = 0; j < 8; ++j)
        asm("mov.b64 {%0, %1}, %2;" : "=f"(e[2*j]), "=f"(e[2*j+1]) : "l"(E[j]));
#pragma unroll
    for (int j = 0; j < 7; ++j)
        asm("mov.b64 {%0, %1}, %2;" : "=f"(q[2*j]), "=f"(q[2*j+1]) : "l"(Q[j]));
    float res[16];
    res[0]  = e[0]  + s0;
    res[15] = e[15] + s15;
#pragma unroll
    for (int j = 0; j < 7; ++j) {
        res[2*j + 1] = e[2*j + 1] + q[2*j];
        res[2*j + 2] = e[2*j + 2] + q[2*j + 1];
    }

    float4* op = (float4*)(out + (size_t)c * VOL + ((size_t)(h0 + hl) * WW + w) * 16);
    op[0] = make_float4(res[0],  res[1],  res[2],  res[3]);
    op[1] = make_float4(res[4],  res[5],  res[6],  res[7]);
    op[2] = make_float4(res[8],  res[9],  res[10], res[11]);
    op[3] = make_float4(res[12], res[13], res[14], res[15]);
}

// -------------------- launch --------------------
extern "C" void kernel_launch(void* const* d_in, const int* in_sizes, int n_in,
                              void* d_out, int out_size) {
    const float* x  = (const float*)d_in[0];
    const float* w7 = (const float*)d_in[1];
    const float* b7 = (const float*)d_in[2];
    const float* w5 = (const float*)d_in[3];
    const float* b5 = (const float*)d_in[4];
    const float* w3 = (const float*)d_in[5];
    const float* b3 = (const float*)d_in[6];
    float* out = (float*)d_out;

    fold_weights_kernel<<<NCH, 256>>>(w7, b7, w5, b5, w3, b3);

    static bool attr_set = false;
    if (!attr_set) {
        cudaFuncSetAttribute(ppeg_conv_kernel,
                             cudaFuncAttributeMaxDynamicSharedMemorySize, SMEM_BYTES);
        attr_set = true;
    }

    dim3 grid(HH / 4, NCH);   // 16 h-tiles x 512 channels
    ppeg_conv_kernel<<<grid, NTHR, SMEM_BYTES>>>(x, out);
}

// round 9
// speedup vs baseline: 1.1630x; 1.1630x over previous
#include <cuda_runtime.h>
#include <cuda_bf16.h>
#include <cstdint>

// ---------------------------------------------------------------------------
// PPEG: out = dwconv7(x) + x + dwconv5(x) + dwconv3(x)  (depthwise, per-channel)
// Folded into ONE 7x7x7 depthwise conv per channel + combined bias.
//
// Halo-free d-columns: smem stores only gd=0..15 (16 floats, 8 LDS.64/column),
// and only the 100 valid MACs per (dh,dw) column are executed:
//   t = dd-3. Even t (dd 1,3,5)  -> aligned output pairs E_j=(out2j,out2j+1),
//   odd  t (dd 0,2,4,6)          -> staggered pairs Q_j=(out2j+1,out2j+2),
//   both with ALIGNED zv input pairs (no repack movs) + 4 scalar edge taps.
//
// x layout  (per channel c): volume[d][h][w], d=16, h=64, w=64 (w contiguous)
// out layout(per channel c): [h][w][d] with d contiguous (stride-1)
// ---------------------------------------------------------------------------

#define NCH   512
#define DD    16
#define HH    64
#define WW    64
#define VOL   (DD*HH*WW)      // 65536 per channel

#define WSTRIDE 352           // per-channel slot in g_wcomb (343 taps + bias)
__device__ float g_wcomb[NCH * WSTRIDE];

typedef unsigned long long u64;
typedef unsigned int u32;

#define FMA2P(acc_, alo_, ahi_, w2_) \
    asm("{\n\t.reg .b64 _a;\n\tmov.b64 _a, {%1, %2};\n\t" \
        "fma.rn.f32x2 %0, _a, %3, %0;\n\t}" \
        : "+l"(acc_) : "f"(alo_), "f"(ahi_), "l"(w2_))

// -------------------- weight folding --------------------
__global__ void fold_weights_kernel(const float* __restrict__ w7,
                                    const float* __restrict__ b7,
                                    const float* __restrict__ w5,
                                    const float* __restrict__ b5,
                                    const float* __restrict__ w3,
                                    const float* __restrict__ b3) {
    int c = blockIdx.x;
    for (int t = threadIdx.x; t < 343; t += blockDim.x) {
        int dd = t / 49;
        int r  = t % 49;
        int dh = r / 7;
        int dw = r % 7;
        float v = w7[c * 343 + t];
        if (dd >= 1 && dd <= 5 && dh >= 1 && dh <= 5 && dw >= 1 && dw <= 5)
            v += w5[c * 125 + (dd - 1) * 25 + (dh - 1) * 5 + (dw - 1)];
        if (dd >= 2 && dd <= 4 && dh >= 2 && dh <= 4 && dw >= 2 && dw <= 4)
            v += w3[c * 27 + (dd - 2) * 9 + (dh - 2) * 3 + (dw - 2)];
        if (t == 171) v += 1.0f;   // identity: center tap (3,3,3)
        g_wcomb[c * WSTRIDE + t] = v;
    }
    if (threadIdx.x == 0)
        g_wcomb[c * WSTRIDE + 343] = b7[c] + b5[c] + b3[c];
}

// -------------------- main conv --------------------
// CTA: one channel, 4 consecutive h rows, full W, full D.  256 threads.
// Thread (w, hl): one output column of 16 d-values at h = h0+hl.
// Smem tile d-innermost (NO d halo): [sh=10][sw=70][sd_pad=18], gd = 0..15.
// Column stride 18 words: 18w mod 32 gives 16 distinct even banks per 16-lane
// LDS.64 phase -> conflict-free.
#define SDP   18
#define SM_H  10
#define SM_W  70
#define NCOLS (SM_H * SM_W)                  // 700 (sh,sw) columns
#define TILE_FLOATS (NCOLS * SDP)            // 12600
#define WT_U64S (49 * 8)                     // 392 u64 (7 dd + pad per (dh,dw))
#define SMEM_BYTES (TILE_FLOATS * 4 + WT_U64S * 8 + 16)   // ~53.6 KB
#define NTHR  256

__global__ __launch_bounds__(NTHR, 3)
void ppeg_conv_kernel(const float* __restrict__ x, float* __restrict__ out) {
    extern __shared__ float smem[];
    float* sx  = smem;                        // input tile, d-innermost, no d-halo
    u64*  swt2 = (u64*)(smem + TILE_FLOATS);  // weight pairs, [(dh*7+dw)*8 + dd]
    float* sbias = (float*)(swt2 + WT_U64S);

    const int c   = blockIdx.y;
    const int h0  = blockIdx.x * 4;
    const int tid = threadIdx.x;

    const float* __restrict__ xc = x + (size_t)c * VOL;

    // folded weights for this channel -> duplicated pairs, grouped per (dh,dw)
    for (int t = tid; t < 343; t += NTHR) {
        int dd = t / 49;               // original layout [dd][dh][dw]
        int r  = t % 49;               // r = dh*7+dw
        float wv = g_wcomb[c * WSTRIDE + t];
        ((float2*)swt2)[r * 8 + dd] = make_float2(wv, wv);
    }
    if (tid == 0) sbias[0] = g_wcomb[c * WSTRIDE + 343];

    // ---- tile load: one (sh,sw) column of 16 d-values per iteration ----
    for (int col = tid; col < NCOLS; col += NTHR) {
        int sh = col / SM_W;
        int sw = col - sh * SM_W;
        int gh = h0 + sh - 3;
        int gw = sw - 3;
        bool okhw = ((unsigned)gh < (unsigned)HH) && ((unsigned)gw < (unsigned)WW);
        const float* gp = xc + (gh * WW + gw);

        float z[16];
#pragma unroll
        for (int gd = 0; gd < 16; ++gd)
            z[gd] = okhw ? __ldg(gp + gd * (HH * WW)) : 0.0f;

        float2* sp = (float2*)(sx + col * SDP);   // 8B aligned (18*4 % 8 == 0)
#pragma unroll
        for (int m = 0; m < 8; ++m)
            sp[m] = make_float2(z[2 * m], z[2 * m + 1]);
    }
    __syncthreads();

    const int w  = tid & 63;   // 0..63
    const int hl = tid >> 6;   // 0..3  -> output at h0+hl

    // E pairs (out0,out1)..(out14,out15) seeded with bias; Q pairs (out1,out2)..
    // (out13,out14); s0/s15 = odd-t edge scalars for out0 / out15.
    u64 E[8], Q[7];
    float s0 = 0.0f, s15 = 0.0f;
    {
        float b = sbias[0];
        u64 b2; asm("mov.b64 %0, {%1, %2};" : "=l"(b2) : "f"(b), "f"(b));
#pragma unroll
        for (int j = 0; j < 8; ++j) E[j] = b2;
#pragma unroll
        for (int j = 0; j < 7; ++j) Q[j] = 0ull;
    }

#pragma unroll 1
    for (int dh = 0; dh < 7; ++dh) {
        const float* rowbase = sx + ((hl + dh) * SM_W + w) * SDP;
        const u64*   wbase   = swt2 + (dh * 7) * 8;
#pragma unroll
        for (int dw = 0; dw < 7; ++dw) {
            // 16-deep d-column as 8 LDS.64
            float2 zv[8];
            const float2* col2 = (const float2*)(rowbase + dw * SDP);
#pragma unroll
            for (int m = 0; m < 8; ++m) zv[m] = col2[m];

            const u64* wcol = wbase + dw * 8;   // 7 contiguous dd pairs

            // ---- E group: even t (dd = 1,3,5), aligned pairs ----
            {
                const u64 w1 = wcol[1];          // t = -2: E_j <- zv[j-1], j=1..7
#pragma unroll
                for (int j = 1; j < 8; ++j) FMA2P(E[j], zv[j-1].x, zv[j-1].y, w1);
                const u64 w3 = wcol[3];          // t =  0: E_j <- zv[j],   j=0..7
#pragma unroll
                for (int j = 0; j < 8; ++j) FMA2P(E[j], zv[j].x, zv[j].y, w3);
                const u64 w5 = wcol[5];          // t = +2: E_j <- zv[j+1], j=0..6
#pragma unroll
                for (int j = 0; j < 7; ++j) FMA2P(E[j], zv[j+1].x, zv[j+1].y, w5);
            }
            // ---- Q group: odd t (dd = 0,2,4,6), staggered pairs ----
            {
                const u64 w0 = wcol[0];          // t = -3: Q_j <- zv[j-1], j=1..6
#pragma unroll
                for (int j = 1; j < 7; ++j) FMA2P(Q[j], zv[j-1].x, zv[j-1].y, w0);
                const u64 w2 = wcol[2];          // t = -1: Q_j <- zv[j],   j=0..6
#pragma unroll
                for (int j = 0; j < 7; ++j) FMA2P(Q[j], zv[j].x, zv[j].y, w2);
                const u64 w4 = wcol[4];          // t = +1: Q_j <- zv[j+1], j=0..6
#pragma unroll
                for (int j = 0; j < 7; ++j) FMA2P(Q[j], zv[j+1].x, zv[j+1].y, w4);
                const u64 w6 = wcol[6];          // t = +3: Q_j <- zv[j+2], j=0..5
#pragma unroll
                for (int j = 0; j < 6; ++j) FMA2P(Q[j], zv[j+2].x, zv[j+2].y, w6);

                // edge scalars (weights are (w,w) pairs: lo half == value)
                float w0s, w2s, w4s, w6s, junk;
                asm("mov.b64 {%0, %1}, %2;" : "=f"(w0s), "=f"(junk) : "l"(w0));
                asm("mov.b64 {%0, %1}, %2;" : "=f"(w2s), "=f"(junk) : "l"(w2));
                asm("mov.b64 {%0, %1}, %2;" : "=f"(w4s), "=f"(junk) : "l"(w4));
                asm("mov.b64 {%0, %1}, %2;" : "=f"(w6s), "=f"(junk) : "l"(w6));
                s0  = fmaf(zv[0].y, w4s, s0);    // out0:  t=+1 -> z1
                s0  = fmaf(zv[1].y, w6s, s0);    // out0:  t=+3 -> z3
                s15 = fmaf(zv[6].x, w0s, s15);   // out15: t=-3 -> z12
                s15 = fmaf(zv[7].x, w2s, s15);   // out15: t=-1 -> z14
            }
        }
    }

    // merge E/Q banks and store: out[c][(h*64+w)*16 + d]
    float e[16], q[14];
#pragma unroll
    for (int j = 0; j < 8; ++j)
        asm("mov.b64 {%0, %1}, %2;" : "=f"(e[2*j]), "=f"(e[2*j+1]) : "l"(E[j]));
#pragma unroll
    for (int j = 0; j < 7; ++j)
        asm("mov.b64 {%0, %1}, %2;" : "=f"(q[2*j]), "=f"(q[2*j+1]) : "l"(Q[j]));
    float res[16];
    res[0]  = e[0]  + s0;
    res[15] = e[15] + s15;
#pragma unroll
    for (int j = 0; j < 7; ++j) {
        res[2*j + 1] = e[2*j + 1] + q[2*j];
        res[2*j + 2] = e[2*j + 2] + q[2*j + 1];
    }

    float4* op = (float4*)(out + (size_t)c * VOL + ((size_t)(h0 + hl) * WW + w) * 16);
    op[0] = make_float4(res[0],  res[1],  res[2],  res[3]);
    op[1] = make_float4(res[4],  res[5],  res[6],  res[7]);
    op[2] = make_float4(res[8],  res[9],  res[10], res[11]);
    op[3] = make_float4(res[12], res[13], res[14], res[15]);
}

// -------------------- launch --------------------
extern "C" void kernel_launch(void* const* d_in, const int* in_sizes, int n_in,
                              void* d_out, int out_size) {
    const float* x  = (const float*)d_in[0];
    const float* w7 = (const float*)d_in[1];
    const float* b7 = (const float*)d_in[2];
    const float* w5 = (const float*)d_in[3];
    const float* b5 = (const float*)d_in[4];
    const float* w3 = (const float*)d_in[5];
    const float* b3 = (const float*)d_in[6];
    float* out = (float*)d_out;

    fold_weights_kernel<<<NCH, 256>>>(w7, b7, w5, b5, w3, b3);

    static bool attr_set = false;
    if (!attr_set) {
        cudaFuncSetAttribute(ppeg_conv_kernel,
                             cudaFuncAttributeMaxDynamicSharedMemorySize, SMEM_BYTES);
        attr_set = true;
    }

    dim3 grid(HH / 4, NCH);   // 16 h-tiles x 512 channels
    ppeg_conv_kernel<<<grid, NTHR, SMEM_BYTES>>>(x, out);
}

// round 10
// speedup vs baseline: 1.1638x; 1.0007x over previous
#include <cuda_runtime.h>
#include <cuda_bf16.h>
#include <cstdint>

// ---------------------------------------------------------------------------
// PPEG: out = dwconv7(x) + x + dwconv5(x) + dwconv3(x)  (depthwise, per-channel)
// Folded into ONE 7x7x7 depthwise conv per channel + combined bias.
//
// Halo-free d-columns (gd=0..15 only, 8 LDS.64/column), 100 valid MACs/column:
//   t = dd-3. Even t (dd 1,3,5) -> aligned output pairs  E_j=(out2j,out2j+1),
//   odd  t (dd 0,2,4,6)         -> staggered pairs       Q_j=(out2j+1,out2j+2),
//   all with ALIGNED zv input pairs (no repack movs) + 4 scalar edge taps.
// 4 CTAs/SM (32 warps) via 64-register cap.
//
// x layout  (per channel c): volume[d][h][w], d=16, h=64, w=64 (w contiguous)
// out layout(per channel c): [h][w][d] with d contiguous (stride-1)
// ---------------------------------------------------------------------------

#define NCH   512
#define DD    16
#define HH    64
#define WW    64
#define VOL   (DD*HH*WW)      // 65536 per channel

#define WSTRIDE 352           // per-channel slot in g_wcomb (343 taps + bias)
__device__ float g_wcomb[NCH * WSTRIDE];

typedef unsigned long long u64;
typedef unsigned int u32;

#define FMA2P(acc_, alo_, ahi_, w2_) \
    asm("{\n\t.reg .b64 _a;\n\tmov.b64 _a, {%1, %2};\n\t" \
        "fma.rn.f32x2 %0, _a, %3, %0;\n\t}" \
        : "+l"(acc_) : "f"(alo_), "f"(ahi_), "l"(w2_))

// -------------------- weight folding --------------------
__global__ void fold_weights_kernel(const float* __restrict__ w7,
                                    const float* __restrict__ b7,
                                    const float* __restrict__ w5,
                                    const float* __restrict__ b5,
                                    const float* __restrict__ w3,
                                    const float* __restrict__ b3) {
    int c = blockIdx.x;
    for (int t = threadIdx.x; t < 343; t += blockDim.x) {
        int dd = t / 49;
        int r  = t % 49;
        int dh = r / 7;
        int dw = r % 7;
        float v = w7[c * 343 + t];
        if (dd >= 1 && dd <= 5 && dh >= 1 && dh <= 5 && dw >= 1 && dw <= 5)
            v += w5[c * 125 + (dd - 1) * 25 + (dh - 1) * 5 + (dw - 1)];
        if (dd >= 2 && dd <= 4 && dh >= 2 && dh <= 4 && dw >= 2 && dw <= 4)
            v += w3[c * 27 + (dd - 2) * 9 + (dh - 2) * 3 + (dw - 2)];
        if (t == 171) v += 1.0f;   // identity: center tap (3,3,3)
        g_wcomb[c * WSTRIDE + t] = v;
    }
    if (threadIdx.x == 0)
        g_wcomb[c * WSTRIDE + 343] = b7[c] + b5[c] + b3[c];
}

// -------------------- main conv --------------------
// CTA: one channel, 4 consecutive h rows, full W, full D.  256 threads.
// Thread (w, hl): one output column of 16 d-values at h = h0+hl.
// Smem tile d-innermost (NO d halo): [sh=10][sw=70][sd_pad=18], gd = 0..15.
// Column stride 18 words: conflict-free LDS.64 (16 distinct banks per phase).
#define SDP   18
#define SM_H  10
#define SM_W  70
#define NCOLS (SM_H * SM_W)                  // 700 (sh,sw) columns
#define TILE_FLOATS (NCOLS * SDP)            // 12600
#define WT_U64S (49 * 8)                     // 392 u64 (7 dd + pad per (dh,dw))
#define SMEM_BYTES (TILE_FLOATS * 4 + WT_U64S * 8 + 16)   // ~53.6 KB
#define NTHR  256

__global__ __launch_bounds__(NTHR, 4)
void ppeg_conv_kernel(const float* __restrict__ x, float* __restrict__ out) {
    extern __shared__ float smem[];
    float* sx  = smem;                        // input tile, d-innermost, no d-halo
    u64*  swt2 = (u64*)(smem + TILE_FLOATS);  // weight pairs, [(dh*7+dw)*8 + dd]
    float* sbias = (float*)(swt2 + WT_U64S);

    const int c   = blockIdx.y;
    const int h0  = blockIdx.x * 4;
    const int tid = threadIdx.x;

    const float* __restrict__ xc = x + (size_t)c * VOL;

    // folded weights for this channel -> duplicated pairs, grouped per (dh,dw)
    for (int t = tid; t < 343; t += NTHR) {
        int dd = t / 49;               // original layout [dd][dh][dw]
        int r  = t % 49;               // r = dh*7+dw
        float wv = g_wcomb[c * WSTRIDE + t];
        ((float2*)swt2)[r * 8 + dd] = make_float2(wv, wv);
    }
    if (tid == 0) sbias[0] = g_wcomb[c * WSTRIDE + 343];

    // ---- tile load: one (sh,sw) column of 16 d-values per iteration ----
    for (int col = tid; col < NCOLS; col += NTHR) {
        int sh = col / SM_W;
        int sw = col - sh * SM_W;
        int gh = h0 + sh - 3;
        int gw = sw - 3;
        bool okhw = ((unsigned)gh < (unsigned)HH) && ((unsigned)gw < (unsigned)WW);
        const float* gp = xc + (gh * WW + gw);

        float2* sp = (float2*)(sx + col * SDP);   // 8B aligned
#pragma unroll
        for (int m = 0; m < 8; ++m) {
            float a = okhw ? __ldg(gp + (2 * m) * (HH * WW)) : 0.0f;
            float b = okhw ? __ldg(gp + (2 * m + 1) * (HH * WW)) : 0.0f;
            sp[m] = make_float2(a, b);
        }
    }
    __syncthreads();

    const int w  = tid & 63;   // 0..63
    const int hl = tid >> 6;   // 0..3  -> output at h0+hl

    // E pairs (out0,out1)..(out14,out15) seeded with bias; Q pairs (out1,out2)..
    // (out13,out14); s0/s15 = odd-t edge scalars for out0 / out15.
    u64 E[8], Q[7];
    float s0 = 0.0f, s15 = 0.0f;
    {
        float b = sbias[0];
        u64 b2; asm("mov.b64 %0, {%1, %2};" : "=l"(b2) : "f"(b), "f"(b));
#pragma unroll
        for (int j = 0; j < 8; ++j) E[j] = b2;
#pragma unroll
        for (int j = 0; j < 7; ++j) Q[j] = 0ull;
    }

    // single induction pointer: row base advances by SM_W*SDP per dh
    const float* rowptr = sx + ((hl + 0) * SM_W + w) * SDP;
    const u64*   wptr   = swt2;

#pragma unroll 1
    for (int dh = 0; dh < 7; ++dh) {
#pragma unroll
        for (int dw = 0; dw < 7; ++dw) {
            // 16-deep d-column as 8 LDS.64
            float2 zv[8];
            const float2* col2 = (const float2*)(rowptr + dw * SDP);
#pragma unroll
            for (int m = 0; m < 8; ++m) zv[m] = col2[m];

            const u64* wcol = wptr + dw * 8;   // 7 contiguous dd pairs

            // ---- E group: even t (dd = 1,3,5), aligned pairs ----
            {
                const u64 w1 = wcol[1];          // t = -2: E_j <- zv[j-1], j=1..7
#pragma unroll
                for (int j = 1; j < 8; ++j) FMA2P(E[j], zv[j-1].x, zv[j-1].y, w1);
                const u64 w3 = wcol[3];          // t =  0: E_j <- zv[j],   j=0..7
#pragma unroll
                for (int j = 0; j < 8; ++j) FMA2P(E[j], zv[j].x, zv[j].y, w3);
                const u64 w5 = wcol[5];          // t = +2: E_j <- zv[j+1], j=0..6
#pragma unroll
                for (int j = 0; j < 7; ++j) FMA2P(E[j], zv[j+1].x, zv[j+1].y, w5);
            }
            // ---- Q group: odd t (dd = 0,2,4,6), staggered pairs ----
            {
                const u64 w0 = wcol[0];          // t = -3: Q_j <- zv[j-1], j=1..6
#pragma unroll
                for (int j = 1; j < 7; ++j) FMA2P(Q[j], zv[j-1].x, zv[j-1].y, w0);
                const u64 w2 = wcol[2];          // t = -1: Q_j <- zv[j],   j=0..6
#pragma unroll
                for (int j = 0; j < 7; ++j) FMA2P(Q[j], zv[j].x, zv[j].y, w2);
                const u64 w4 = wcol[4];          // t = +1: Q_j <- zv[j+1], j=0..6
#pragma unroll
                for (int j = 0; j < 7; ++j) FMA2P(Q[j], zv[j+1].x, zv[j+1].y, w4);
                const u64 w6 = wcol[6];          // t = +3: Q_j <- zv[j+2], j=0..5
#pragma unroll
                for (int j = 0; j < 6; ++j) FMA2P(Q[j], zv[j+2].x, zv[j+2].y, w6);

                // edge scalars (weights are (w,w) pairs: halves equal)
                float w0s, w2s, w4s, w6s, junk;
                asm("mov.b64 {%0, %1}, %2;" : "=f"(w0s), "=f"(junk) : "l"(w0));
                asm("mov.b64 {%0, %1}, %2;" : "=f"(w2s), "=f"(junk) : "l"(w2));
                asm("mov.b64 {%0, %1}, %2;" : "=f"(w4s), "=f"(junk) : "l"(w4));
                asm("mov.b64 {%0, %1}, %2;" : "=f"(w6s), "=f"(junk) : "l"(w6));
                s0  = fmaf(zv[0].y, w4s, s0);    // out0:  t=+1 -> z1
                s0  = fmaf(zv[1].y, w6s, s0);    // out0:  t=+3 -> z3
                s15 = fmaf(zv[6].x, w0s, s15);   // out15: t=-3 -> z12
                s15 = fmaf(zv[7].x, w2s, s15);   // out15: t=-1 -> z14
            }
        }
        rowptr += SM_W * SDP;
        wptr   += 7 * 8;
    }

    // merge E/Q banks and store: out[c][(h*64+w)*16 + d]
    float e[16], q[14];
#pragma unroll
    for (int j = 0; j < 8; ++j)
        asm("mov.b64 {%0, %1}, %2;" : "=f"(e[2*j]), "=f"(e[2*j+1]) : "l"(E[j]));
#pragma unroll
    for (int j = 0; j < 7; ++j)
        asm("mov.b64 {%0, %1}, %2;" : "=f"(q[2*j]), "=f"(q[2*j+1]) : "l"(Q[j]));
    float res[16];
    res[0]  = e[0]  + s0;
    res[15] = e[15] + s15;
#pragma unroll
    for (int j = 0; j < 7; ++j) {
        res[2*j + 1] = e[2*j + 1] + q[2*j];
        res[2*j + 2] = e[2*j + 2] + q[2*j + 1];
    }

    float4* op = (float4*)(out + (size_t)c * VOL + ((size_t)(h0 + hl) * WW + w) * 16);
    op[0] = make_float4(res[0],  res[1],  res[2],  res[3]);
    op[1] = make_float4(res[4],  res[5],  res[6],  res[7]);
    op[2] = make_float4(res[8],  res[9],  res[10], res[11]);
    op[3] = make_float4(res[12], res[13], res[14], res[15]);
}

// -------------------- launch --------------------
extern "C" void kernel_launch(void* const* d_in, const int* in_sizes, int n_in,
                              void* d_out, int out_size) {
    const float* x  = (const float*)d_in[0];
    const float* w7 = (const float*)d_in[1];
    const float* b7 = (const float*)d_in[2];
    const float* w5 = (const float*)d_in[3];
    const float* b5 = (const float*)d_in[4];
    const float* w3 = (const float*)d_in[5];
    const float* b3 = (const float*)d_in[6];
    float* out = (float*)d_out;

    fold_weights_kernel<<<NCH, 256>>>(w7, b7, w5, b5, w3, b3);

    static bool attr_set = false;
    if (!attr_set) {
        cudaFuncSetAttribute(ppeg_conv_kernel,
                             cudaFuncAttributeMaxDynamicSharedMemorySize, SMEM_BYTES);
        attr_set = true;
    }

    dim3 grid(HH / 4, NCH);   // 16 h-tiles x 512 channels
    ppeg_conv_kernel<<<grid, NTHR, SMEM_BYTES>>>(x, out);
}

// round 11
// speedup vs baseline: 1.3276x; 1.1408x over previous
#include <cuda_runtime.h>
#include <cuda_bf16.h>
#include <cstdint>

// ---------------------------------------------------------------------------
// PPEG: out = dwconv7(x) + x + dwconv5(x) + dwconv3(x)  (depthwise, per-channel)
// Folded into ONE 7x7x7 depthwise conv per channel + combined bias.
//
// Halo-free d-columns (gd=0..15, 8 LDS.64/column), 100 valid MACs per column:
//   t = dd-3. Even t (dd 1,3,5) -> aligned output pairs  E_j=(out2j,out2j+1),
//   odd  t (dd 0,2,4,6)         -> staggered pairs       Q_j=(out2j+1,out2j+2),
//   all ALIGNED zv input pairs (no repack movs) + 4 scalar edge taps.
//
// dh-reuse: each thread computes 2 adjacent h-outputs (A at h, B at h+1);
// a column at row dhp feeds A with weights(dhp) and B with weights(dhp-1).
// Loop dw OUTER, dhp INNER: weight row rotates in registers -> each weight
// u64 pair is loaded ONCE and serves both banks. Weights loaded vectorized
// (3x LDS.128 + 1x LDS.64 per 7-pair group).
//
// x layout  (per channel c): volume[d][h][w], d=16, h=64, w=64 (w contiguous)
// out layout(per channel c): [h][w][d] with d contiguous (stride-1)
// ---------------------------------------------------------------------------

#define NCH   512
#define DD    16
#define HH    64
#define WW    64
#define VOL   (DD*HH*WW)      // 65536 per channel

#define WSTRIDE 352           // per-channel slot in g_wcomb (343 taps + bias)
__device__ float g_wcomb[NCH * WSTRIDE];

typedef unsigned long long u64;
typedef unsigned int u32;

#define FMA2P(acc_, alo_, ahi_, w2_) \
    asm("{\n\t.reg .b64 _a;\n\tmov.b64 _a, {%1, %2};\n\t" \
        "fma.rn.f32x2 %0, _a, %3, %0;\n\t}" \
        : "+l"(acc_) : "f"(alo_), "f"(ahi_), "l"(w2_))

// -------------------- weight folding --------------------
__global__ void fold_weights_kernel(const float* __restrict__ w7,
                                    const float* __restrict__ b7,
                                    const float* __restrict__ w5,
                                    const float* __restrict__ b5,
                                    const float* __restrict__ w3,
                                    const float* __restrict__ b3) {
    int c = blockIdx.x;
    for (int t = threadIdx.x; t < 343; t += blockDim.x) {
        int dd = t / 49;
        int r  = t % 49;
        int dh = r / 7;
        int dw = r % 7;
        float v = w7[c * 343 + t];
        if (dd >= 1 && dd <= 5 && dh >= 1 && dh <= 5 && dw >= 1 && dw <= 5)
            v += w5[c * 125 + (dd - 1) * 25 + (dh - 1) * 5 + (dw - 1)];
        if (dd >= 2 && dd <= 4 && dh >= 2 && dh <= 4 && dw >= 2 && dw <= 4)
            v += w3[c * 27 + (dd - 2) * 9 + (dh - 2) * 3 + (dw - 2)];
        if (t == 171) v += 1.0f;   // identity: center tap (3,3,3)
        g_wcomb[c * WSTRIDE + t] = v;
    }
    if (threadIdx.x == 0)
        g_wcomb[c * WSTRIDE + 343] = b7[c] + b5[c] + b3[c];
}

// -------------------- main conv --------------------
// CTA: one channel, 8 consecutive h rows, full W, full D.  256 threads.
// Thread (w, hq): outputs at h = h0+2hq (A) and h0+2hq+1 (B).
// Smem tile d-innermost (NO d halo): [sh=14][sw=70][sd_pad=18], gd = 0..15.
// Column stride 18 words: conflict-free LDS.64.
#define SDP   18
#define SM_H  14
#define SM_W  70
#define NCOLS (SM_H * SM_W)                  // 980 (sh,sw) columns
#define TILE_FLOATS (NCOLS * SDP)            // 17640
#define WT_U64S (49 * 8)                     // 392 u64 (7 dd + pad per (dh,dw))
#define SMEM_BYTES (TILE_FLOATS * 4 + WT_U64S * 8 + 16)   // ~73.7 KB
#define NTHR  256

// load 7 contiguous u64 weight pairs (3x LDS.128 + 1x LDS.64, broadcast)
__device__ __forceinline__ void load_w7(const u64* __restrict__ p, u64 wv[7]) {
    ulonglong2 ab = *(const ulonglong2*)(p);
    ulonglong2 cd = *(const ulonglong2*)(p + 2);
    ulonglong2 ef = *(const ulonglong2*)(p + 4);
    wv[0] = ab.x; wv[1] = ab.y;
    wv[2] = cd.x; wv[3] = cd.y;
    wv[4] = ef.x; wv[5] = ef.y;
    wv[6] = p[6];
}

// apply 100 valid MACs of one column (zv, 16 d-values) to one accumulator bank
__device__ __forceinline__ void acc_col(const float2 zv[8], const u64 wv[7],
                                        u64 E[8], u64 Q[7],
                                        float& s0, float& s15) {
    // E group: even t (dd = 1,3,5), aligned output pairs
#pragma unroll
    for (int j = 1; j < 8; ++j) FMA2P(E[j], zv[j-1].x, zv[j-1].y, wv[1]);  // t=-2
#pragma unroll
    for (int j = 0; j < 8; ++j) FMA2P(E[j], zv[j].x,   zv[j].y,   wv[3]);  // t= 0
#pragma unroll
    for (int j = 0; j < 7; ++j) FMA2P(E[j], zv[j+1].x, zv[j+1].y, wv[5]);  // t=+2
    // Q group: odd t (dd = 0,2,4,6), staggered output pairs
#pragma unroll
    for (int j = 1; j < 7; ++j) FMA2P(Q[j], zv[j-1].x, zv[j-1].y, wv[0]);  // t=-3
#pragma unroll
    for (int j = 0; j < 7; ++j) FMA2P(Q[j], zv[j].x,   zv[j].y,   wv[2]);  // t=-1
#pragma unroll
    for (int j = 0; j < 7; ++j) FMA2P(Q[j], zv[j+1].x, zv[j+1].y, wv[4]);  // t=+1
#pragma unroll
    for (int j = 0; j < 6; ++j) FMA2P(Q[j], zv[j+2].x, zv[j+2].y, wv[6]);  // t=+3
    // edge scalars (weights are (w,w) duplicated pairs: lo half == value)
    float w0s, w2s, w4s, w6s, junk;
    asm("mov.b64 {%0, %1}, %2;" : "=f"(w0s), "=f"(junk) : "l"(wv[0]));
    asm("mov.b64 {%0, %1}, %2;" : "=f"(w2s), "=f"(junk) : "l"(wv[2]));
    asm("mov.b64 {%0, %1}, %2;" : "=f"(w4s), "=f"(junk) : "l"(wv[4]));
    asm("mov.b64 {%0, %1}, %2;" : "=f"(w6s), "=f"(junk) : "l"(wv[6]));
    s0  = fmaf(zv[0].y, w4s, s0);    // out0:  t=+1 -> z1
    s0  = fmaf(zv[1].y, w6s, s0);    // out0:  t=+3 -> z3
    s15 = fmaf(zv[6].x, w0s, s15);   // out15: t=-3 -> z12
    s15 = fmaf(zv[7].x, w2s, s15);   // out15: t=-1 -> z14
}

__device__ __forceinline__ void store16(float* __restrict__ out, size_t base,
                                        const u64 E[8], const u64 Q[7],
                                        float s0, float s15) {
    float e[16], q[14];
#pragma unroll
    for (int j = 0; j < 8; ++j)
        asm("mov.b64 {%0, %1}, %2;" : "=f"(e[2*j]), "=f"(e[2*j+1]) : "l"(E[j]));
#pragma unroll
    for (int j = 0; j < 7; ++j)
        asm("mov.b64 {%0, %1}, %2;" : "=f"(q[2*j]), "=f"(q[2*j+1]) : "l"(Q[j]));
    float res[16];
    res[0]  = e[0]  + s0;
    res[15] = e[15] + s15;
#pragma unroll
    for (int j = 0; j < 7; ++j) {
        res[2*j + 1] = e[2*j + 1] + q[2*j];
        res[2*j + 2] = e[2*j + 2] + q[2*j + 1];
    }
    float4* op = (float4*)(out + base);
    op[0] = make_float4(res[0],  res[1],  res[2],  res[3]);
    op[1] = make_float4(res[4],  res[5],  res[6],  res[7]);
    op[2] = make_float4(res[8],  res[9],  res[10], res[11]);
    op[3] = make_float4(res[12], res[13], res[14], res[15]);
}

__global__ __launch_bounds__(NTHR, 2)
void ppeg_conv_kernel(const float* __restrict__ x, float* __restrict__ out) {
    extern __shared__ float smem[];
    float* sx  = smem;                        // input tile, d-innermost, no d-halo
    u64*  swt2 = (u64*)(smem + TILE_FLOATS);  // weight pairs, [(dh*7+dw)*8 + dd]
    float* sbias = (float*)(swt2 + WT_U64S);

    const int c   = blockIdx.y;
    const int h0  = blockIdx.x * 8;
    const int tid = threadIdx.x;

    const float* __restrict__ xc = x + (size_t)c * VOL;

    // folded weights for this channel -> duplicated pairs, grouped per (dh,dw)
    for (int t = tid; t < 343; t += NTHR) {
        int dd = t / 49;               // original layout [dd][dh][dw]
        int r  = t % 49;               // r = dh*7+dw
        float wv = g_wcomb[c * WSTRIDE + t];
        ((float2*)swt2)[r * 8 + dd] = make_float2(wv, wv);
    }
    if (tid == 0) sbias[0] = g_wcomb[c * WSTRIDE + 343];

    // ---- tile load: one (sh,sw) column of 16 d-values per iteration ----
    for (int col = tid; col < NCOLS; col += NTHR) {
        int sh = col / SM_W;
        int sw = col - sh * SM_W;
        int gh = h0 + sh - 3;
        int gw = sw - 3;
        bool okhw = ((unsigned)gh < (unsigned)HH) && ((unsigned)gw < (unsigned)WW);
        const float* gp = xc + (gh * WW + gw);

        float2* sp = (float2*)(sx + col * SDP);   // 8B aligned
#pragma unroll
        for (int m = 0; m < 8; ++m) {
            float a = okhw ? __ldg(gp + (2 * m) * (HH * WW)) : 0.0f;
            float b = okhw ? __ldg(gp + (2 * m + 1) * (HH * WW)) : 0.0f;
            sp[m] = make_float2(a, b);
        }
    }
    __syncthreads();

    const int w  = tid & 63;   // 0..63
    const int hq = tid >> 6;   // 0..3
    const int shbase = 2 * hq; // bank A at h0+shbase, bank B at h0+shbase+1

    u64 EA[8], QA[7], EB[8], QB[7];
    float s0A = 0.0f, s15A = 0.0f, s0B = 0.0f, s15B = 0.0f;
    {
        float b = sbias[0];
        u64 b2; asm("mov.b64 %0, {%1, %2};" : "=l"(b2) : "f"(b), "f"(b));
#pragma unroll
        for (int j = 0; j < 8; ++j) { EA[j] = b2; EB[j] = b2; }
#pragma unroll
        for (int j = 0; j < 7; ++j) { QA[j] = 0ull; QB[j] = 0ull; }
    }

    // dw OUTER, dhp INNER: column at (row shbase+dhp, col w+dw) feeds
    // bank A with weights(dh=dhp) and bank B with weights(dh=dhp-1).
    // Weight row rotates in registers -> each pair loaded once for both banks.
#pragma unroll 1
    for (int dw = 0; dw < 7; ++dw) {
        const float* colbase = sx + ((size_t)shbase * SM_W + (w + dw)) * SDP;
        const u64*   wbase   = swt2 + dw * 8;      // + dhp*7*8 per row

        u64 wprev[7], wcur[7];
        float2 zv[8];

        // dhp = 0: A only
        {
            const float2* cp = (const float2*)colbase;
#pragma unroll
            for (int m = 0; m < 8; ++m) zv[m] = cp[m];
            load_w7(wbase, wcur);
            acc_col(zv, wcur, EA, QA, s0A, s15A);
#pragma unroll
            for (int i = 0; i < 7; ++i) wprev[i] = wcur[i];
        }
        // dhp = 1..6: A with wcur, B with wprev
#pragma unroll
        for (int dhp = 1; dhp < 7; ++dhp) {
            const float2* cp = (const float2*)(colbase + dhp * (SM_W * SDP));
#pragma unroll
            for (int m = 0; m < 8; ++m) zv[m] = cp[m];
            load_w7(wbase + dhp * 7 * 8, wcur);
            acc_col(zv, wcur,  EA, QA, s0A, s15A);
            acc_col(zv, wprev, EB, QB, s0B, s15B);
#pragma unroll
            for (int i = 0; i < 7; ++i) wprev[i] = wcur[i];
        }
        // dhp = 7: B only
        {
            const float2* cp = (const float2*)(colbase + 7 * (SM_W * SDP));
#pragma unroll
            for (int m = 0; m < 8; ++m) zv[m] = cp[m];
            acc_col(zv, wprev, EB, QB, s0B, s15B);
        }
    }

    // store: out[c][(h*64+w)*16 + d]
    const size_t cb = (size_t)c * VOL;
    store16(out, cb + ((size_t)(h0 + shbase)     * WW + w) * 16, EA, QA, s0A, s15A);
    store16(out, cb + ((size_t)(h0 + shbase + 1) * WW + w) * 16, EB, QB, s0B, s15B);
}

// -------------------- launch --------------------
extern "C" void kernel_launch(void* const* d_in, const int* in_sizes, int n_in,
                              void* d_out, int out_size) {
    const float* x  = (const float*)d_in[0];
    const float* w7 = (const float*)d_in[1];
    const float* b7 = (const float*)d_in[2];
    const float* w5 = (const float*)d_in[3];
    const float* b5 = (const float*)d_in[4];
    const float* w3 = (const float*)d_in[5];
    const float* b3 = (const float*)d_in[6];
    float* out = (float*)d_out;

    fold_weights_kernel<<<NCH, 256>>>(w7, b7, w5, b5, w3, b3);

    static bool attr_set = false;
    if (!attr_set) {
        cudaFuncSetAttribute(ppeg_conv_kernel,
                             cudaFuncAttributeMaxDynamicSharedMemorySize, SMEM_BYTES);
        attr_set = true;
    }

    dim3 grid(HH / 8, NCH);   // 8 h-tiles x 512 channels
    ppeg_conv_kernel<<<grid, NTHR, SMEM_BYTES>>>(x, out);
}